// round 2
// baseline (speedup 1.0000x reference)
#include <cuda_runtime.h>
#include <cstdint>

#define MAXN 50000
#define NRAD 20
#define FCUT 5.0f
#define EPB 128

typedef unsigned long long ull;

__device__ float g_h[(size_t)MAXN * 64];
__device__ float g_so[(size_t)MAXN * 192];

__device__ __forceinline__ ull pk2(float lo, float hi) {
    ull r; asm("mov.b64 %0, {%1, %2};" : "=l"(r) : "f"(lo), "f"(hi)); return r;
}
__device__ __forceinline__ float2 up2(ull a) {
    float2 f; asm("mov.b64 {%0, %1}, %2;" : "=f"(f.x), "=f"(f.y) : "l"(a)); return f;
}
__device__ __forceinline__ ull ffma2(ull a, ull b, ull c) {
    ull d; asm("fma.rn.f32x2 %0, %1, %2, %3;" : "=l"(d) : "l"(a), "l"(b), "l"(c)); return d;
}
__device__ __forceinline__ void lds2x64(ull &a, ull &b, unsigned addr) {
    asm("ld.shared.v2.b64 {%0, %1}, [%2];" : "=l"(a), "=l"(b) : "r"(addr));
}
__device__ __forceinline__ void red4(float* p, float a, float b, float c, float d) {
    asm volatile("red.global.add.v4.f32 [%0], {%1, %2, %3, %4};"
                 :: "l"(p), "f"(a), "f"(b), "f"(c), "f"(d) : "memory");
}
__device__ __forceinline__ float silu_f(float x) {
    return __fdividef(x, 1.0f + __expf(-x));
}

// ---------------------------------------------------------------------------
// Kernel 0: initialize output with node_scalar / node_vector (residual base)
// ---------------------------------------------------------------------------
__global__ void __launch_bounds__(256) k_init(const float4* __restrict__ ns,
                                              const float4* __restrict__ nv,
                                              float4* __restrict__ out,
                                              int n4s, int n4tot) {
    int i = blockIdx.x * 256 + threadIdx.x;
    if (i < n4s)       out[i] = ns[i];
    else if (i < n4tot) out[i] = nv[i - n4s];
}

// ---------------------------------------------------------------------------
// Kernel 1: H = silu(X @ W1 + b1)    (X: N x 64, W1: 64 x 64)
// one node per thread; f32x2 packing over output-channel pairs
// ---------------------------------------------------------------------------
__global__ void __launch_bounds__(128) k_mlp1(const float* __restrict__ X,
                                              const float* __restrict__ W,
                                              const float* __restrict__ b,
                                              int N) {
    __shared__ __align__(16) float sW[64 * 64];
    int t = threadIdx.x;
    {
        const float4* w4 = (const float4*)W;
        float4* s4 = (float4*)sW;
        #pragma unroll
        for (int i = 0; i < 8; i++) s4[t + i * 128] = w4[t + i * 128];
    }
    __syncthreads();
    int n = blockIdx.x * 128 + t;
    if (n >= N) return;

    ull x2[64];
    const float4* xr = (const float4*)(X + (size_t)n * 64);
    #pragma unroll
    for (int i = 0; i < 16; i++) {
        float4 v = xr[i];
        x2[4*i+0] = pk2(v.x, v.x); x2[4*i+1] = pk2(v.y, v.y);
        x2[4*i+2] = pk2(v.z, v.z); x2[4*i+3] = pk2(v.w, v.w);
    }
    unsigned wb = (unsigned)__cvta_generic_to_shared(sW);
    float* hr = g_h + (size_t)n * 64;

    #pragma unroll 1
    for (int jg = 0; jg < 4; jg++) {
        ull acc[8];
        #pragma unroll
        for (int i = 0; i < 8; i++) {
            int j = jg * 16 + 2 * i;
            acc[i] = pk2(__ldg(b + j), __ldg(b + j + 1));
        }
        unsigned a0 = wb + jg * 16 * 4;
        #pragma unroll
        for (int k = 0; k < 64; k++) {
            ull w0,w1,w2,w3,w4,w5,w6,w7;
            unsigned a = a0 + k * 64 * 4;
            lds2x64(w0, w1, a);      lds2x64(w2, w3, a + 16);
            lds2x64(w4, w5, a + 32); lds2x64(w6, w7, a + 48);
            acc[0]=ffma2(x2[k],w0,acc[0]); acc[1]=ffma2(x2[k],w1,acc[1]);
            acc[2]=ffma2(x2[k],w2,acc[2]); acc[3]=ffma2(x2[k],w3,acc[3]);
            acc[4]=ffma2(x2[k],w4,acc[4]); acc[5]=ffma2(x2[k],w5,acc[5]);
            acc[6]=ffma2(x2[k],w6,acc[6]); acc[7]=ffma2(x2[k],w7,acc[7]);
        }
        float o[16];
        #pragma unroll
        for (int i = 0; i < 8; i++) {
            float2 p = up2(acc[i]);
            o[2*i]   = silu_f(p.x);
            o[2*i+1] = silu_f(p.y);
        }
        float4* hv = (float4*)(hr + jg * 16);
        hv[0] = make_float4(o[0],  o[1],  o[2],  o[3]);
        hv[1] = make_float4(o[4],  o[5],  o[6],  o[7]);
        hv[2] = make_float4(o[8],  o[9],  o[10], o[11]);
        hv[3] = make_float4(o[12], o[13], o[14], o[15]);
    }
}

// ---------------------------------------------------------------------------
// Kernel 2: scalar_out = H @ W2 + b2   (H: N x 64, W2: 64 x 192)
// ---------------------------------------------------------------------------
__global__ void __launch_bounds__(128) k_mlp2(const float* __restrict__ W,
                                              const float* __restrict__ b,
                                              int N) {
    __shared__ __align__(16) float sW[64 * 192];   // 48 KB
    int t = threadIdx.x;
    {
        const float4* w4 = (const float4*)W;
        float4* s4 = (float4*)sW;
        for (int i = t; i < 3072; i += 128) s4[i] = w4[i];
    }
    __syncthreads();
    int n = blockIdx.x * 128 + t;
    if (n >= N) return;

    ull x2[64];
    const float4* xr = (const float4*)(g_h + (size_t)n * 64);
    #pragma unroll
    for (int i = 0; i < 16; i++) {
        float4 v = xr[i];
        x2[4*i+0] = pk2(v.x, v.x); x2[4*i+1] = pk2(v.y, v.y);
        x2[4*i+2] = pk2(v.z, v.z); x2[4*i+3] = pk2(v.w, v.w);
    }
    unsigned wb = (unsigned)__cvta_generic_to_shared(sW);
    float* orow = g_so + (size_t)n * 192;

    #pragma unroll 1
    for (int jg = 0; jg < 12; jg++) {
        ull acc[8];
        #pragma unroll
        for (int i = 0; i < 8; i++) {
            int j = jg * 16 + 2 * i;
            acc[i] = pk2(__ldg(b + j), __ldg(b + j + 1));
        }
        unsigned a0 = wb + jg * 16 * 4;
        #pragma unroll
        for (int k = 0; k < 64; k++) {
            ull w0,w1,w2,w3,w4,w5,w6,w7;
            unsigned a = a0 + k * 192 * 4;
            lds2x64(w0, w1, a);      lds2x64(w2, w3, a + 16);
            lds2x64(w4, w5, a + 32); lds2x64(w6, w7, a + 48);
            acc[0]=ffma2(x2[k],w0,acc[0]); acc[1]=ffma2(x2[k],w1,acc[1]);
            acc[2]=ffma2(x2[k],w2,acc[2]); acc[3]=ffma2(x2[k],w3,acc[3]);
            acc[4]=ffma2(x2[k],w4,acc[4]); acc[5]=ffma2(x2[k],w5,acc[5]);
            acc[6]=ffma2(x2[k],w6,acc[6]); acc[7]=ffma2(x2[k],w7,acc[7]);
        }
        float o[16];
        #pragma unroll
        for (int i = 0; i < 8; i++) {
            float2 p = up2(acc[i]);
            o[2*i] = p.x; o[2*i+1] = p.y;
        }
        float4* ov = (float4*)(orow + jg * 16);
        ov[0] = make_float4(o[0],  o[1],  o[2],  o[3]);
        ov[1] = make_float4(o[4],  o[5],  o[6],  o[7]);
        ov[2] = make_float4(o[8],  o[9],  o[10], o[11]);
        ov[3] = make_float4(o[12], o[13], o[14], o[15]);
    }
}

// ---------------------------------------------------------------------------
// Kernel 3: per-edge filter + message + scatter (vectorized RED atomics)
// 16 threads per edge (4 channels each), 128 edges per block
// edge is int32 pairs (JAX x64 disabled -> int64 request materializes int32)
// ---------------------------------------------------------------------------
__global__ void __launch_bounds__(256) k_edge(const int2* __restrict__ edge,
                                              const float* __restrict__ ediff,
                                              const float* __restrict__ edist,
                                              const float* __restrict__ Wf,
                                              const float* __restrict__ bfil,
                                              const float* __restrict__ nvec,
                                              float* __restrict__ out_s,
                                              float* __restrict__ out_v,
                                              int E) {
    __shared__ __align__(16) float sWf[NRAD * 192];
    __shared__ __align__(16) float sbf[192];
    int t = threadIdx.x;
    {
        const float4* w4 = (const float4*)Wf;
        float4* s4 = (float4*)sWf;
        for (int i = t; i < 960; i += 256) s4[i] = w4[i];
        if (t < 48) ((float4*)sbf)[t] = ((const float4*)bfil)[t];
    }
    __syncthreads();

    int eg = t >> 4, lane = t & 15, cbase = lane * 4;
    unsigned wb = (unsigned)__cvta_generic_to_shared(sWf) + cbase * 4;
    int ebase = blockIdx.x * EPB + eg;

    #pragma unroll 1
    for (int it = 0; it < EPB / 16; it++) {
        int e = ebase + it * 16;
        if (e >= E) break;

        int2 ed = edge[e];
        size_t dst = (size_t)(unsigned)ed.x, src = (size_t)(unsigned)ed.y;
        float dist = __ldg(edist + e);
        float invd = __fdividef(1.0f, dist);
        float th = dist * (3.14159265358979f / FCUT);
        float s1, c1;
        __sincosf(th, &s1, &c1);
        float cut = (dist < FCUT) ? 0.5f * (c1 + 1.0f) : 0.0f;

        // filter accumulation: sum_r sin((r+1)*th) * Wf[r][c]  via recurrence
        ull a0v=0, a1v=0, a2v=0, a3v=0, a4v=0, a5v=0;
        float sp = 0.0f, sc = s1;
        float twoc = c1 + c1;
        #pragma unroll
        for (int r = 0; r < NRAD; r++) {
            ull v = pk2(sc, sc);
            ull w0,w1,w2,w3,w4,w5;
            unsigned a = wb + r * (192 * 4);
            lds2x64(w0, w1, a);
            lds2x64(w2, w3, a + 256);
            lds2x64(w4, w5, a + 512);
            a0v = ffma2(v, w0, a0v); a1v = ffma2(v, w1, a1v);
            a2v = ffma2(v, w2, a2v); a3v = ffma2(v, w3, a3v);
            a4v = ffma2(v, w4, a4v); a5v = ffma2(v, w5, a5v);
            float sn = fmaf(twoc, sc, -sp);
            sp = sc; sc = sn;
        }

        float ic = invd * cut;
        float f[12];
        {
            float2 p;
            p = up2(a0v); f[0] = fmaf(p.x, ic, sbf[cbase+0]*cut);   f[1]  = fmaf(p.y, ic, sbf[cbase+1]*cut);
            p = up2(a1v); f[2] = fmaf(p.x, ic, sbf[cbase+2]*cut);   f[3]  = fmaf(p.y, ic, sbf[cbase+3]*cut);
            p = up2(a2v); f[4] = fmaf(p.x, ic, sbf[64+cbase+0]*cut); f[5]  = fmaf(p.y, ic, sbf[64+cbase+1]*cut);
            p = up2(a3v); f[6] = fmaf(p.x, ic, sbf[64+cbase+2]*cut); f[7]  = fmaf(p.y, ic, sbf[64+cbase+3]*cut);
            p = up2(a4v); f[8] = fmaf(p.x, ic, sbf[128+cbase+0]*cut); f[9]  = fmaf(p.y, ic, sbf[128+cbase+1]*cut);
            p = up2(a5v); f[10]= fmaf(p.x, ic, sbf[128+cbase+2]*cut); f[11] = fmaf(p.y, ic, sbf[128+cbase+3]*cut);
        }

        const float* sob = g_so + src * 192 + cbase;
        float4 so0 = *(const float4*)(sob);
        float4 so1 = *(const float4*)(sob + 64);
        float4 so2 = *(const float4*)(sob + 128);

        float gsv0 = f[0]*so0.x, gsv1 = f[1]*so0.y, gsv2 = f[2]*so0.z, gsv3 = f[3]*so0.w;
        float gev0 = f[4]*so1.x, gev1 = f[5]*so1.y, gev2 = f[6]*so1.z, gev3 = f[7]*so1.w;

        // message_scalar scatter
        red4(out_s + dst * 64 + cbase,
             f[8]*so2.x, f[9]*so2.y, f[10]*so2.z, f[11]*so2.w);

        float dx = __ldg(ediff + 3*(size_t)e);
        float dy = __ldg(ediff + 3*(size_t)e + 1);
        float dz = __ldg(ediff + 3*(size_t)e + 2);
        float uu[3] = { dx*invd, dy*invd, dz*invd };

        const float* nvb = nvec + src * 192 + cbase;
        #pragma unroll
        for (int d = 0; d < 3; d++) {
            float4 nv = *(const float4*)(nvb + d * 64);
            red4(out_v + dst * 192 + d * 64 + cbase,
                 fmaf(nv.x, gsv0, gev0 * uu[d]),
                 fmaf(nv.y, gsv1, gev1 * uu[d]),
                 fmaf(nv.z, gsv2, gev2 * uu[d]),
                 fmaf(nv.w, gsv3, gev3 * uu[d]));
        }
    }
}

// ---------------------------------------------------------------------------
extern "C" void kernel_launch(void* const* d_in, const int* in_sizes, int n_in,
                              void* d_out, int out_size) {
    const float* node_scalar = (const float*)d_in[0];
    const float* node_vector = (const float*)d_in[1];
    const int2* edge         = (const int2*)d_in[2];
    const float* edge_diff   = (const float*)d_in[3];
    const float* edge_dist   = (const float*)d_in[4];
    const float* W1          = (const float*)d_in[5];
    const float* b1          = (const float*)d_in[6];
    const float* W2          = (const float*)d_in[7];
    const float* b2          = (const float*)d_in[8];
    const float* Wf          = (const float*)d_in[9];
    const float* bf          = (const float*)d_in[10];

    int N = in_sizes[0] / 64;
    int E = in_sizes[2] / 2;

    float* out   = (float*)d_out;
    float* out_v = out + (size_t)N * 64;

    int n4s = N * 16;          // float4 count of scalar part
    int n4tot = N * 64;        // float4 count of full output

    k_init<<<(n4tot + 255) / 256, 256>>>((const float4*)node_scalar,
                                         (const float4*)node_vector,
                                         (float4*)out, n4s, n4tot);
    k_mlp1<<<(N + 127) / 128, 128>>>(node_scalar, W1, b1, N);
    k_mlp2<<<(N + 127) / 128, 128>>>(W2, b2, N);
    k_edge<<<(E + EPB - 1) / EPB, 256>>>(edge, edge_diff, edge_dist,
                                         Wf, bf, node_vector,
                                         out, out_v, E);
}

// round 4
// speedup vs baseline: 1.2728x; 1.2728x over previous
#include <cuda_runtime.h>
#include <cstdint>

#define MAXN 50000
#define NRAD 20
#define FCUT 5.0f
#define T_E   48      // edges per block (k_edge)
#define PAIRS 24

typedef unsigned long long ull;

__device__ float g_h[(size_t)MAXN * 64];
__device__ float g_so[(size_t)MAXN * 192];

__device__ __forceinline__ ull pk2(float lo, float hi) {
    ull r; asm("mov.b64 %0, {%1, %2};" : "=l"(r) : "f"(lo), "f"(hi)); return r;
}
__device__ __forceinline__ float2 up2(ull a) {
    float2 f; asm("mov.b64 {%0, %1}, %2;" : "=f"(f.x), "=f"(f.y) : "l"(a)); return f;
}
__device__ __forceinline__ ull ffma2(ull a, ull b, ull c) {
    ull d; asm("fma.rn.f32x2 %0, %1, %2, %3;" : "=l"(d) : "l"(a), "l"(b), "l"(c)); return d;
}
__device__ __forceinline__ ull mul2(ull a, ull b) {
    ull d; asm("mul.rn.f32x2 %0, %1, %2;" : "=l"(d) : "l"(a), "l"(b)); return d;
}
__device__ __forceinline__ ull add2(ull a, ull b) {
    ull d; asm("add.rn.f32x2 %0, %1, %2;" : "=l"(d) : "l"(a), "l"(b)); return d;
}
__device__ __forceinline__ void lds2x64(ull &a, ull &b, unsigned addr) {
    asm("ld.shared.v2.b64 {%0, %1}, [%2];" : "=l"(a), "=l"(b) : "r"(addr));
}
__device__ __forceinline__ ull lds64(unsigned addr) {
    ull v; asm("ld.shared.b64 %0, [%1];" : "=l"(v) : "r"(addr)); return v;
}
__device__ __forceinline__ void red4(float* p, float a, float b, float c, float d) {
    asm volatile("red.global.add.v4.f32 [%0], {%1, %2, %3, %4};"
                 :: "l"(p), "f"(a), "f"(b), "f"(c), "f"(d) : "memory");
}
__device__ __forceinline__ float silu_f(float x) {
    return __fdividef(x, 1.0f + __expf(-x));
}

// ---------------------------------------------------------------------------
// Kernel 0: initialize output with node_scalar / node_vector (residual base)
// ---------------------------------------------------------------------------
__global__ void __launch_bounds__(256) k_init(const float4* __restrict__ ns,
                                              const float4* __restrict__ nv,
                                              float4* __restrict__ out,
                                              int n4s, int n4tot) {
    int i = blockIdx.x * 256 + threadIdx.x;
    if (i < n4s)       out[i] = ns[i];
    else if (i < n4tot) out[i] = nv[i - n4s];
}

// ---------------------------------------------------------------------------
// Kernel 1: H = silu(X @ W1 + b1)    (X: N x 64, W1: 64 x 64)
// ---------------------------------------------------------------------------
__global__ void __launch_bounds__(128) k_mlp1(const float* __restrict__ X,
                                              const float* __restrict__ W,
                                              const float* __restrict__ b,
                                              int N) {
    __shared__ __align__(16) float sW[64 * 64];
    int t = threadIdx.x;
    {
        const float4* w4 = (const float4*)W;
        float4* s4 = (float4*)sW;
        #pragma unroll
        for (int i = 0; i < 8; i++) s4[t + i * 128] = w4[t + i * 128];
    }
    __syncthreads();
    int n = blockIdx.x * 128 + t;
    if (n >= N) return;

    ull x2[64];
    const float4* xr = (const float4*)(X + (size_t)n * 64);
    #pragma unroll
    for (int i = 0; i < 16; i++) {
        float4 v = xr[i];
        x2[4*i+0] = pk2(v.x, v.x); x2[4*i+1] = pk2(v.y, v.y);
        x2[4*i+2] = pk2(v.z, v.z); x2[4*i+3] = pk2(v.w, v.w);
    }
    unsigned wb = (unsigned)__cvta_generic_to_shared(sW);
    float* hr = g_h + (size_t)n * 64;

    #pragma unroll 1
    for (int jg = 0; jg < 4; jg++) {
        ull acc[8];
        #pragma unroll
        for (int i = 0; i < 8; i++) {
            int j = jg * 16 + 2 * i;
            acc[i] = pk2(__ldg(b + j), __ldg(b + j + 1));
        }
        unsigned a0 = wb + jg * 16 * 4;
        #pragma unroll
        for (int k = 0; k < 64; k++) {
            ull w0,w1,w2,w3,w4,w5,w6,w7;
            unsigned a = a0 + k * 64 * 4;
            lds2x64(w0, w1, a);      lds2x64(w2, w3, a + 16);
            lds2x64(w4, w5, a + 32); lds2x64(w6, w7, a + 48);
            acc[0]=ffma2(x2[k],w0,acc[0]); acc[1]=ffma2(x2[k],w1,acc[1]);
            acc[2]=ffma2(x2[k],w2,acc[2]); acc[3]=ffma2(x2[k],w3,acc[3]);
            acc[4]=ffma2(x2[k],w4,acc[4]); acc[5]=ffma2(x2[k],w5,acc[5]);
            acc[6]=ffma2(x2[k],w6,acc[6]); acc[7]=ffma2(x2[k],w7,acc[7]);
        }
        float o[16];
        #pragma unroll
        for (int i = 0; i < 8; i++) {
            float2 p = up2(acc[i]);
            o[2*i]   = silu_f(p.x);
            o[2*i+1] = silu_f(p.y);
        }
        float4* hv = (float4*)(hr + jg * 16);
        hv[0] = make_float4(o[0],  o[1],  o[2],  o[3]);
        hv[1] = make_float4(o[4],  o[5],  o[6],  o[7]);
        hv[2] = make_float4(o[8],  o[9],  o[10], o[11]);
        hv[3] = make_float4(o[12], o[13], o[14], o[15]);
    }
}

// ---------------------------------------------------------------------------
// Kernel 2: scalar_out = H @ W2 + b2   (H: N x 64, W2: 64 x 192)
// ---------------------------------------------------------------------------
__global__ void __launch_bounds__(128) k_mlp2(const float* __restrict__ W,
                                              const float* __restrict__ b,
                                              int N) {
    __shared__ __align__(16) float sW[64 * 192];   // 48 KB
    int t = threadIdx.x;
    {
        const float4* w4 = (const float4*)W;
        float4* s4 = (float4*)sW;
        for (int i = t; i < 3072; i += 128) s4[i] = w4[i];
    }
    __syncthreads();
    int n = blockIdx.x * 128 + t;
    if (n >= N) return;

    ull x2[64];
    const float4* xr = (const float4*)(g_h + (size_t)n * 64);
    #pragma unroll
    for (int i = 0; i < 16; i++) {
        float4 v = xr[i];
        x2[4*i+0] = pk2(v.x, v.x); x2[4*i+1] = pk2(v.y, v.y);
        x2[4*i+2] = pk2(v.z, v.z); x2[4*i+3] = pk2(v.w, v.w);
    }
    unsigned wb = (unsigned)__cvta_generic_to_shared(sW);
    float* orow = g_so + (size_t)n * 192;

    #pragma unroll 1
    for (int jg = 0; jg < 12; jg++) {
        ull acc[8];
        #pragma unroll
        for (int i = 0; i < 8; i++) {
            int j = jg * 16 + 2 * i;
            acc[i] = pk2(__ldg(b + j), __ldg(b + j + 1));
        }
        unsigned a0 = wb + jg * 16 * 4;
        #pragma unroll
        for (int k = 0; k < 64; k++) {
            ull w0,w1,w2,w3,w4,w5,w6,w7;
            unsigned a = a0 + k * 192 * 4;
            lds2x64(w0, w1, a);      lds2x64(w2, w3, a + 16);
            lds2x64(w4, w5, a + 32); lds2x64(w6, w7, a + 48);
            acc[0]=ffma2(x2[k],w0,acc[0]); acc[1]=ffma2(x2[k],w1,acc[1]);
            acc[2]=ffma2(x2[k],w2,acc[2]); acc[3]=ffma2(x2[k],w3,acc[3]);
            acc[4]=ffma2(x2[k],w4,acc[4]); acc[5]=ffma2(x2[k],w5,acc[5]);
            acc[6]=ffma2(x2[k],w6,acc[6]); acc[7]=ffma2(x2[k],w7,acc[7]);
        }
        float o[16];
        #pragma unroll
        for (int i = 0; i < 8; i++) {
            float2 p = up2(acc[i]);
            o[2*i] = p.x; o[2*i+1] = p.y;
        }
        float4* ov = (float4*)(orow + jg * 16);
        ov[0] = make_float4(o[0],  o[1],  o[2],  o[3]);
        ov[1] = make_float4(o[4],  o[5],  o[6],  o[7]);
        ov[2] = make_float4(o[8],  o[9],  o[10], o[11]);
        ov[3] = make_float4(o[12], o[13], o[14], o[15]);
    }
}

// ---------------------------------------------------------------------------
// Kernel 3: per-edge filter + message + scatter, 3-phase tile.
//   Phase A0: 48 threads, per-edge sincos + sin recurrence -> shared
//   Phase A : 192 threads = 192 channels, Wf column in registers (f32x2,
//             edge-pair packed), broadcast LDS of sins -> sF in shared
//   Phase B : 12 slots x 16 lanes, gather g_so/nvec, red4 scatter
// ---------------------------------------------------------------------------
__global__ void __launch_bounds__(192, 4) k_edge(const int2* __restrict__ edge,
                                                 const float* __restrict__ ediff,
                                                 const float* __restrict__ edist,
                                                 const float* __restrict__ Wf,
                                                 const float* __restrict__ bfil,
                                                 const float* __restrict__ nvec,
                                                 float* __restrict__ out_s,
                                                 float* __restrict__ out_v,
                                                 int E) {
    __shared__ __align__(16) float sS[PAIRS * 40];   // sins: [pair][radial][edge-in-pair]
    __shared__ __align__(16) float sIC[T_E];         // cut/dist per edge (pair-adjacent)
    __shared__ __align__(16) float sCut[T_E];
    __shared__ __align__(16) float sF[T_E * 192];    // filter weights per edge
    __shared__ int   sDst[T_E], sSrc[T_E];
    __shared__ float sUx[T_E], sUy[T_E], sUz[T_E];

    int t = threadIdx.x;
    int base = blockIdx.x * T_E;

    // Wf column c = t, prepacked for edge-pair f32x2 math
    ull wfp[NRAD]; ull bfp;
    #pragma unroll
    for (int r = 0; r < NRAD; r++) {
        float w = __ldg(Wf + r * 192 + t);
        wfp[r] = pk2(w, w);
    }
    { float bv = __ldg(bfil + t); bfp = pk2(bv, bv); }

    // ---- Phase A0 ----
    if (t < T_E) {
        int e = base + t;
        bool valid = e < E;
        int2 ed = valid ? edge[e] : make_int2(0, 0);
        float dist = valid ? __ldg(edist + e) : 1.0f;
        float invd = __fdividef(1.0f, dist);
        float th = dist * (3.14159265358979f / FCUT);
        float s1, c1;
        __sincosf(th, &s1, &c1);
        float cut = (valid && dist < FCUT) ? 0.5f * (c1 + 1.0f) : 0.0f;
        float dx = 0.f, dy = 0.f, dz = 0.f;
        if (valid) {
            dx = __ldg(ediff + 3*(size_t)e);
            dy = __ldg(ediff + 3*(size_t)e + 1);
            dz = __ldg(ediff + 3*(size_t)e + 2);
        }
        sDst[t] = ed.x; sSrc[t] = ed.y;
        sIC[t] = invd * cut; sCut[t] = cut;
        sUx[t] = dx * invd; sUy[t] = dy * invd; sUz[t] = dz * invd;

        float sp = 0.0f, sc = s1, twoc = c1 + c1;
        float* sp_out = sS + (t >> 1) * 40 + (t & 1);
        #pragma unroll
        for (int r = 0; r < NRAD; r++) {
            sp_out[2 * r] = sc;
            float sn = fmaf(twoc, sc, -sp);
            sp = sc; sc = sn;
        }
    }
    __syncthreads();

    // ---- Phase A ----
    {
        unsigned sSb  = (unsigned)__cvta_generic_to_shared(sS);
        unsigned sICb = (unsigned)__cvta_generic_to_shared(sIC);
        unsigned sCb  = (unsigned)__cvta_generic_to_shared(sCut);
        float* fc = sF + t;
        #pragma unroll 2
        for (int p = 0; p < PAIRS; p++) {
            ull a0 = 0, a1 = 0;
            unsigned a = sSb + p * 160;
            #pragma unroll
            for (int r = 0; r < NRAD; r += 2) {
                ull s0, s1v;
                lds2x64(s0, s1v, a + r * 8);
                a0 = ffma2(s0,  wfp[r],     a0);
                a1 = ffma2(s1v, wfp[r + 1], a1);
            }
            ull acc = add2(a0, a1);
            ull ic2  = lds64(sICb + p * 8);
            ull cut2 = lds64(sCb  + p * 8);
            ull f2 = ffma2(acc, ic2, mul2(bfp, cut2));
            float2 f = up2(f2);
            fc[(2 * p) * 192]     = f.x;
            fc[(2 * p + 1) * 192] = f.y;
        }
    }
    __syncthreads();

    // ---- Phase B ----
    {
        int slot = t >> 4, lane = t & 15, cbase = lane * 4;
        #pragma unroll 1
        for (int k = 0; k < 4; k++) {
            int le = slot * 4 + k;
            int e = base + le;
            if (e >= E) break;
            size_t dst = (size_t)(unsigned)sDst[le];
            size_t src = (size_t)(unsigned)sSrc[le];
            float uu[3] = { sUx[le], sUy[le], sUz[le] };

            const float* fp = sF + le * 192 + cbase;
            float4 f0 = *(const float4*)(fp);
            float4 f1 = *(const float4*)(fp + 64);
            float4 f2v = *(const float4*)(fp + 128);

            const float* sob = g_so + src * 192 + cbase;
            float4 so0 = *(const float4*)(sob);
            float4 so1 = *(const float4*)(sob + 64);
            float4 so2 = *(const float4*)(sob + 128);

            float gsv0 = f0.x*so0.x, gsv1 = f0.y*so0.y, gsv2 = f0.z*so0.z, gsv3 = f0.w*so0.w;
            float gev0 = f1.x*so1.x, gev1 = f1.y*so1.y, gev2 = f1.z*so1.z, gev3 = f1.w*so1.w;

            red4(out_s + dst * 64 + cbase,
                 f2v.x*so2.x, f2v.y*so2.y, f2v.z*so2.z, f2v.w*so2.w);

            const float* nvb = nvec + src * 192 + cbase;
            #pragma unroll
            for (int d = 0; d < 3; d++) {
                float4 nv = *(const float4*)(nvb + d * 64);
                red4(out_v + dst * 192 + d * 64 + cbase,
                     fmaf(nv.x, gsv0, gev0 * uu[d]),
                     fmaf(nv.y, gsv1, gev1 * uu[d]),
                     fmaf(nv.z, gsv2, gev2 * uu[d]),
                     fmaf(nv.w, gsv3, gev3 * uu[d]));
            }
        }
    }
}

// ---------------------------------------------------------------------------
extern "C" void kernel_launch(void* const* d_in, const int* in_sizes, int n_in,
                              void* d_out, int out_size) {
    const float* node_scalar = (const float*)d_in[0];
    const float* node_vector = (const float*)d_in[1];
    const int2* edge         = (const int2*)d_in[2];
    const float* edge_diff   = (const float*)d_in[3];
    const float* edge_dist   = (const float*)d_in[4];
    const float* W1          = (const float*)d_in[5];
    const float* b1          = (const float*)d_in[6];
    const float* W2          = (const float*)d_in[7];
    const float* b2          = (const float*)d_in[8];
    const float* Wf          = (const float*)d_in[9];
    const float* bf          = (const float*)d_in[10];

    int N = in_sizes[0] / 64;
    int E = in_sizes[2] / 2;

    float* out   = (float*)d_out;
    float* out_v = out + (size_t)N * 64;

    int n4s = N * 16;
    int n4tot = N * 64;

    k_init<<<(n4tot + 255) / 256, 256>>>((const float4*)node_scalar,
                                         (const float4*)node_vector,
                                         (float4*)out, n4s, n4tot);
    k_mlp1<<<(N + 127) / 128, 128>>>(node_scalar, W1, b1, N);
    k_mlp2<<<(N + 127) / 128, 128>>>(W2, b2, N);
    k_edge<<<(E + T_E - 1) / T_E, 192>>>(edge, edge_diff, edge_dist,
                                         Wf, bf, node_vector,
                                         out, out_v, E);
}